// round 8
// baseline (speedup 1.0000x reference)
#include <cuda_runtime.h>

// mailbox: [N=50000, DEG=32, FEAT=128] float32 -> out[n][f] = mean over deg.
//
// Pure HBM-bound stream (~845MB, zero reuse). R5 baseline: 125.7us, 86.9% DRAM.
// This round:
//  - persistent single-wave grid (148 SMs x 8 blocks = 1184 blocks, grid-stride)
//    eliminates ~5 wave transitions (~2360cyc each) and per-wave tail drain
//  - __ldcs / __stcs streaming hints: data is read/written exactly once, so
//    evict-first keeps L2 from thrashing sector state on a pure stream
//
// One thread per (node, float4-column): warp = exactly one 512B neighbor row,
// every LDG.128 a full coalesced line; fully-unrolled deg loop for MLP.

#define N_NODES 50000
#define MAX_DEG 32
#define FEAT4   32                      // 128 floats / 4
#define TOTAL4  (N_NODES * FEAT4)       // 1,600,000 float4 outputs

#define NUM_SMS    148
#define BLOCKS_SM  8
#define THREADS    256
#define GRID       (NUM_SMS * BLOCKS_SM)   // 1184 blocks = exactly one wave

__global__ void __launch_bounds__(THREADS, BLOCKS_SM)
mean_agg_kernel(const float4* __restrict__ mailbox, float4* __restrict__ out) {
    const float inv = 1.0f / (float)MAX_DEG;
    const int stride = GRID * THREADS;

    for (int idx = blockIdx.x * THREADS + threadIdx.x; idx < TOTAL4; idx += stride) {
        int n  = idx >> 5;          // / FEAT4
        int f4 = idx & 31;          // % FEAT4

        const float4* p = mailbox + ((long long)n * (MAX_DEG * FEAT4)) + f4;

        float4 acc = make_float4(0.f, 0.f, 0.f, 0.f);
#pragma unroll
        for (int d = 0; d < MAX_DEG; ++d) {
            float4 v = __ldcs(&p[d * FEAT4]);   // evict-first: read-once stream
            acc.x += v.x;
            acc.y += v.y;
            acc.z += v.z;
            acc.w += v.w;
        }

        acc.x *= inv; acc.y *= inv; acc.z *= inv; acc.w *= inv;
        __stcs(&out[idx], acc);                  // streaming store
    }
}

extern "C" void kernel_launch(void* const* d_in, const int* in_sizes, int n_in,
                              void* d_out, int out_size) {
    const float4* mailbox = (const float4*)d_in[0];
    float4* out = (float4*)d_out;
    mean_agg_kernel<<<GRID, THREADS>>>(mailbox, out);
}